// round 1
// baseline (speedup 1.0000x reference)
#include <cuda_runtime.h>

#define NN 100000
#define EE 1250000
#define DD 64
#define LL 5
#define GG 128
#define TT 37
#define DE 7

// ---------------- device scratch (no allocations allowed) ----------------
__device__ float d_hbuf[LL * NN * DD];   // 128 MB: per-layer node embeddings
__device__ float d_agg[NN * DD];         // 25.6 MB: (1+eps)*h + sum of messages
__device__ int   d_src[EE];
__device__ int   d_dst[EE];
__device__ int   d_batch32[NN];
__device__ float d_gpool[GG * LL * DD];  // pooled graph features [128, 320]
__device__ int   d_flags[2];             // [0]=edge_index is int64, [1]=batch is int64

// ---------------- dtype detection (int64 vs int32 index arrays) ----------
// For a little-endian int64 array of small non-negative values, every odd
// 32-bit word is 0. For int32 data those words are random indices.
__global__ void detect_kernel(const unsigned* __restrict__ ei,
                              const unsigned* __restrict__ batch) {
    if (threadIdx.x == 0 && blockIdx.x == 0) {
        int f = 1;
        for (int k = 0; k < 64; k++) {
            if (ei[1000001 + 2 * k] != 0u) { f = 0; break; }
        }
        d_flags[0] = f;
        int fb = 1;
        // sample odd word indices near the END (batch is sorted; tail != 0 for int32)
        for (int k = 0; k < 64; k++) {
            if (batch[(NN - 1) - 2 * k] != 0u) { fb = 0; break; }
        }
        d_flags[1] = fb;
    }
}

__global__ void convert_kernel(const void* __restrict__ ei,
                               const void* __restrict__ batch) {
    int i = blockIdx.x * blockDim.x + threadIdx.x;
    int e64 = d_flags[0];
    int b64 = d_flags[1];
    if (i < EE) {
        if (e64) {
            const long long* p = (const long long*)ei;
            d_src[i] = (int)p[i];
            d_dst[i] = (int)p[i + EE];
        } else {
            const int* p = (const int*)ei;
            d_src[i] = p[i];
            d_dst[i] = p[i + EE];
        }
    }
    if (i < NN) {
        if (b64) {
            const long long* p = (const long long*)batch;
            d_batch32[i] = (int)p[i];
        } else {
            const int* p = (const int*)batch;
            d_batch32[i] = p[i];
        }
    }
}

// ---------------- agg = (1 + eps[l]) * h_prev ----------------------------
__global__ void pre_kernel(const float* __restrict__ hprev,
                           const float* __restrict__ eps, int l) {
    int i = blockIdx.x * blockDim.x + threadIdx.x;  // float4 index
    const int n4 = NN * DD / 4;
    if (i >= n4) return;
    float s = 1.0f + __ldg(eps + l);
    float4 v = ((const float4*)hprev)[i];
    v.x *= s; v.y *= s; v.z *= s; v.w *= s;
    ((float4*)d_agg)[i] = v;
}

// ---------------- scatter: agg[dst] += relu(h[src] + edge_emb) ------------
// Half-warp per edge: lane handles 4 consecutive columns -> float4 gather,
// edge encoder recomputed on the fly (7 MACs/col), vectorized red.v4.f32.
__global__ void scatter_kernel(const float* __restrict__ hprev,
                               const float* __restrict__ eattr,
                               const float* __restrict__ We,
                               const float* __restrict__ be) {
    int t = blockIdx.x * blockDim.x + threadIdx.x;
    int lane = threadIdx.x & 31;
    long long e = ((long long)(t >> 5)) * 2 + (lane >> 4);
    if (e >= EE) return;
    int c = (lane & 15) * 4;

    int src = __ldg(&d_src[e]);
    int dst = __ldg(&d_dst[e]);

    const float* ea = eattr + e * DE;
    float a0 = __ldg(ea + 0), a1 = __ldg(ea + 1), a2 = __ldg(ea + 2),
          a3 = __ldg(ea + 3), a4 = __ldg(ea + 4), a5 = __ldg(ea + 5),
          a6 = __ldg(ea + 6);

    float4 hv = *(const float4*)(hprev + (size_t)src * DD + c);

    float m[4];
#pragma unroll
    for (int j = 0; j < 4; j++) {
        int cc = c + j;
        float em = __ldg(be + cc);
        em += a0 * __ldg(We + 0 * DD + cc);
        em += a1 * __ldg(We + 1 * DD + cc);
        em += a2 * __ldg(We + 2 * DD + cc);
        em += a3 * __ldg(We + 3 * DD + cc);
        em += a4 * __ldg(We + 4 * DD + cc);
        em += a5 * __ldg(We + 5 * DD + cc);
        em += a6 * __ldg(We + 6 * DD + cc);
        m[j] = em;
    }
    m[0] = fmaxf(m[0] + hv.x, 0.0f);
    m[1] = fmaxf(m[1] + hv.y, 0.0f);
    m[2] = fmaxf(m[2] + hv.z, 0.0f);
    m[3] = fmaxf(m[3] + hv.w, 0.0f);

    float* ap = d_agg + (size_t)dst * DD + c;
    asm volatile("red.global.add.v4.f32 [%0], {%1,%2,%3,%4};"
                 :: "l"(ap), "f"(m[0]), "f"(m[1]), "f"(m[2]), "f"(m[3])
                 : "memory");
}

// ---------------- MLP: h_out = relu(agg @ W + b) --------------------------
// Block = 256 threads, 32 nodes/block. W (16KB) + u tile (8KB) in smem.
__global__ void mlp_kernel(const float* __restrict__ W,
                           const float* __restrict__ b,
                           float* __restrict__ hout) {
    __shared__ float Ws[DD * DD];
    __shared__ float bs[DD];
    __shared__ float u[32 * DD];

    int t = threadIdx.x;
    for (int i = t; i < DD * DD; i += 256) Ws[i] = W[i];
    if (t < DD) bs[t] = b[t];

    int node0 = blockIdx.x * 32;
    const float4* aggp = (const float4*)(d_agg + (size_t)node0 * DD);
    float4* u4 = (float4*)u;
    for (int i = t; i < 32 * DD / 4; i += 256) u4[i] = aggp[i];
    __syncthreads();

    int warp = t >> 5, lane = t & 31;
    int c = lane * 2;
#pragma unroll
    for (int it = 0; it < 4; it++) {
        int nl = warp + it * 8;           // node-local 0..31
        int node = node0 + nl;
        float acc0 = bs[c], acc1 = bs[c + 1];
        const float* ur = u + nl * DD;
#pragma unroll 16
        for (int k = 0; k < DD; k++) {
            float uv = ur[k];
            float2 w = *(const float2*)(Ws + k * DD + c);
            acc0 += uv * w.x;
            acc1 += uv * w.y;
        }
        float2 o;
        o.x = fmaxf(acc0, 0.0f);
        o.y = fmaxf(acc1, 0.0f);
        *(float2*)(hout + (size_t)node * DD + c) = o;
    }
}

// ---------------- per-graph mean pool ------------------------------------
__device__ __forceinline__ int lower_bound_i(const int* a, int n, int v) {
    int lo = 0, hi = n;
    while (lo < hi) {
        int m = (lo + hi) >> 1;
        if (a[m] < v) lo = m + 1; else hi = m;
    }
    return lo;
}

__global__ void pool_kernel() {
    int g = blockIdx.x;
    int c = threadIdx.x;                 // 0..319
    int start = lower_bound_i(d_batch32, NN, g);
    int end   = lower_bound_i(d_batch32, NN, g + 1);
    int l = c >> 6, d = c & 63;
    const float* hp = d_hbuf + (size_t)l * NN * DD;
    float s = 0.0f;
    for (int n = start; n < end; n++) s += hp[(size_t)n * DD + d];
    float cnt = (float)(end - start);
    if (cnt < 1.0f) cnt = 1.0f;
    d_gpool[g * (LL * DD) + c] = s / cnt;
}

// ---------------- predictor: out = gpool @ W_pred + b_pred ----------------
__global__ void pred_kernel(const float* __restrict__ Wp,
                            const float* __restrict__ bp,
                            float* __restrict__ out) {
    int i = blockIdx.x * blockDim.x + threadIdx.x;
    if (i >= GG * TT) return;
    int g = i / TT, t = i % TT;
    float acc = __ldg(bp + t);
    const float* gp = d_gpool + g * (LL * DD);
    for (int c = 0; c < LL * DD; c++)
        acc += gp[c] * __ldg(Wp + c * TT + t);
    out[i] = acc;
}

// ---------------- launch -------------------------------------------------
extern "C" void kernel_launch(void* const* d_in, const int* in_sizes, int n_in,
                              void* d_out, int out_size) {
    const float* x     = (const float*)d_in[0];
    const void*  ei    = d_in[1];
    const float* eattr = (const float*)d_in[2];
    const void*  batch = d_in[3];
    const float* We    = (const float*)d_in[4];
    const float* be    = (const float*)d_in[5];
    const float* eps   = (const float*)d_in[6];
    const float* Wm    = (const float*)d_in[7];
    const float* bm    = (const float*)d_in[8];
    const float* Wp    = (const float*)d_in[9];
    const float* bp    = (const float*)d_in[10];
    float* out = (float*)d_out;

    detect_kernel<<<1, 32>>>((const unsigned*)ei, (const unsigned*)batch);
    convert_kernel<<<(EE + 255) / 256, 256>>>(ei, batch);

    float* hbuf = nullptr;
    cudaGetSymbolAddress((void**)&hbuf, d_hbuf);

    const float* hprev = x;
    for (int l = 0; l < LL; l++) {
        pre_kernel<<<(NN * DD / 4 + 255) / 256, 256>>>(hprev, eps, l);
        // 2 edges per warp, 8 warps per block
        scatter_kernel<<<(EE / 2 + 7) / 8, 256>>>(hprev, eattr, We, be);
        float* hout = hbuf + (size_t)l * NN * DD;
        mlp_kernel<<<NN / 32, 256>>>(Wm + l * DD * DD, bm + l * DD, hout);
        hprev = hout;
    }

    pool_kernel<<<GG, LL * DD>>>();
    pred_kernel<<<(GG * TT + 255) / 256, 256>>>(Wp, bp, out);
}

// round 2
// speedup vs baseline: 1.3333x; 1.3333x over previous
#include <cuda_runtime.h>

#define NN 100000
#define EE 1250000
#define DD 64
#define LL 5
#define GG 128
#define TT 37
#define DE 7

// ---------------- device scratch (no allocations allowed) ----------------
__device__ float d_hbuf[LL * NN * DD];    // per-layer node embeddings
__device__ float d_agg[NN * DD];          // (1+eps)*h + sum of messages
__device__ int2  d_edge[EE];              // packed {src,dst}
__device__ float d_eattr8[EE * 8];        // edge_attr padded to 8 floats, 16B aligned
__device__ int   d_batch32[NN];
__device__ float d_gpool[GG * LL * DD];
__device__ int   d_flags[2];              // [0]=edge_index int64, [1]=batch int64

// ---------------- dtype detection (int64 vs int32 index arrays) ----------
__global__ void detect_kernel(const unsigned* __restrict__ ei,
                              const unsigned* __restrict__ batch) {
    if (threadIdx.x == 0 && blockIdx.x == 0) {
        int f = 1;
        for (int k = 0; k < 64; k++)
            if (ei[1000001 + 2 * k] != 0u) { f = 0; break; }
        d_flags[0] = f;
        int fb = 1;
        for (int k = 0; k < 64; k++)
            if (batch[(NN - 1) - 2 * k] != 0u) { fb = 0; break; }
        d_flags[1] = fb;
    }
}

// convert indices + pack edge_attr to [E,8]
__global__ void convert_kernel(const void* __restrict__ ei,
                               const void* __restrict__ batch,
                               const float* __restrict__ eattr) {
    int i = blockIdx.x * blockDim.x + threadIdx.x;
    int e64 = d_flags[0];
    int b64 = d_flags[1];
    if (i < EE) {
        int s, d;
        if (e64) {
            const long long* p = (const long long*)ei;
            s = (int)p[i]; d = (int)p[i + EE];
        } else {
            const int* p = (const int*)ei;
            s = p[i]; d = p[i + EE];
        }
        d_edge[i] = make_int2(s, d);
        const float* ea = eattr + (size_t)i * DE;
        float4 v0 = make_float4(ea[0], ea[1], ea[2], ea[3]);
        float4 v1 = make_float4(ea[4], ea[5], ea[6], 0.0f);
        ((float4*)(d_eattr8 + (size_t)i * 8))[0] = v0;
        ((float4*)(d_eattr8 + (size_t)i * 8))[1] = v1;
    }
    if (i < NN) {
        if (b64) {
            const long long* p = (const long long*)batch;
            d_batch32[i] = (int)p[i];
        } else {
            const int* p = (const int*)batch;
            d_batch32[i] = p[i];
        }
    }
}

// ---------------- agg = (1 + eps[0]) * x  (layer 0 only) ------------------
__global__ void pre_kernel(const float* __restrict__ hprev,
                           const float* __restrict__ eps) {
    int i = blockIdx.x * blockDim.x + threadIdx.x;
    const int n4 = NN * DD / 4;
    if (i >= n4) return;
    float s = 1.0f + __ldg(eps);
    float4 v = ((const float4*)hprev)[i];
    v.x *= s; v.y *= s; v.z *= s; v.w *= s;
    ((float4*)d_agg)[i] = v;
}

// ---------------- scatter: agg[dst] += relu(h[src] + edge_emb) ------------
// Half-warp per edge, grid-stride. Each thread owns 4 fixed columns and keeps
// its W_edge slice (7 float4) + bias in REGISTERS across the edge loop.
__global__ void __launch_bounds__(256) scatter_kernel(
        const float* __restrict__ hprev,
        const float* __restrict__ We,
        const float* __restrict__ be) {
    int lane = threadIdx.x & 31;
    int c = (lane & 15) * 4;

    float4 w0 = *(const float4*)(We + 0 * DD + c);
    float4 w1 = *(const float4*)(We + 1 * DD + c);
    float4 w2 = *(const float4*)(We + 2 * DD + c);
    float4 w3 = *(const float4*)(We + 3 * DD + c);
    float4 w4 = *(const float4*)(We + 4 * DD + c);
    float4 w5 = *(const float4*)(We + 5 * DD + c);
    float4 w6 = *(const float4*)(We + 6 * DD + c);
    float4 bv = *(const float4*)(be + c);

    int t = blockIdx.x * blockDim.x + threadIdx.x;
    long long hw = ((long long)(t >> 5)) * 2 + (lane >> 4);   // half-warp id
    long long nhw = ((long long)gridDim.x * blockDim.x / 32) * 2;

    for (long long e = hw; e < EE; e += nhw) {
        int2 sd = __ldg(&d_edge[e]);
        float4 ea0 = *(const float4*)(d_eattr8 + (size_t)e * 8);
        float4 ea1 = *(const float4*)(d_eattr8 + (size_t)e * 8 + 4);
        float4 hv = *(const float4*)(hprev + (size_t)sd.x * DD + c);

        float m0 = bv.x, m1 = bv.y, m2 = bv.z, m3 = bv.w;
        m0 = fmaf(ea0.x, w0.x, m0); m1 = fmaf(ea0.x, w0.y, m1);
        m2 = fmaf(ea0.x, w0.z, m2); m3 = fmaf(ea0.x, w0.w, m3);
        m0 = fmaf(ea0.y, w1.x, m0); m1 = fmaf(ea0.y, w1.y, m1);
        m2 = fmaf(ea0.y, w1.z, m2); m3 = fmaf(ea0.y, w1.w, m3);
        m0 = fmaf(ea0.z, w2.x, m0); m1 = fmaf(ea0.z, w2.y, m1);
        m2 = fmaf(ea0.z, w2.z, m2); m3 = fmaf(ea0.z, w2.w, m3);
        m0 = fmaf(ea0.w, w3.x, m0); m1 = fmaf(ea0.w, w3.y, m1);
        m2 = fmaf(ea0.w, w3.z, m2); m3 = fmaf(ea0.w, w3.w, m3);
        m0 = fmaf(ea1.x, w4.x, m0); m1 = fmaf(ea1.x, w4.y, m1);
        m2 = fmaf(ea1.x, w4.z, m2); m3 = fmaf(ea1.x, w4.w, m3);
        m0 = fmaf(ea1.y, w5.x, m0); m1 = fmaf(ea1.y, w5.y, m1);
        m2 = fmaf(ea1.y, w5.z, m2); m3 = fmaf(ea1.y, w5.w, m3);
        m0 = fmaf(ea1.z, w6.x, m0); m1 = fmaf(ea1.z, w6.y, m1);
        m2 = fmaf(ea1.z, w6.z, m2); m3 = fmaf(ea1.z, w6.w, m3);

        m0 = fmaxf(m0 + hv.x, 0.0f);
        m1 = fmaxf(m1 + hv.y, 0.0f);
        m2 = fmaxf(m2 + hv.z, 0.0f);
        m3 = fmaxf(m3 + hv.w, 0.0f);

        float* ap = d_agg + (size_t)sd.y * DD + c;
        asm volatile("red.global.add.v4.f32 [%0], {%1,%2,%3,%4};"
                     :: "l"(ap), "f"(m0), "f"(m1), "f"(m2), "f"(m3)
                     : "memory");
    }
}

// ---------------- MLP: h_out = relu(agg @ W + b); agg_next = s*h_out ------
__global__ void mlp_kernel(const float* __restrict__ W,
                           const float* __restrict__ b,
                           float* __restrict__ hout,
                           const float* __restrict__ eps, int l) {
    __shared__ float Ws[DD * DD];
    __shared__ float bs[DD];
    __shared__ float u[32 * DD];

    int t = threadIdx.x;
    for (int i = t; i < DD * DD; i += 256) Ws[i] = W[i];
    if (t < DD) bs[t] = b[t];

    int node0 = blockIdx.x * 32;
    const float4* aggp = (const float4*)(d_agg + (size_t)node0 * DD);
    float4* u4 = (float4*)u;
    for (int i = t; i < 32 * DD / 4; i += 256) u4[i] = aggp[i];
    __syncthreads();

    float snext = (l < LL - 1) ? (1.0f + __ldg(eps + l + 1)) : 0.0f;

    int warp = t >> 5, lane = t & 31;
    int c = lane * 2;
#pragma unroll
    for (int it = 0; it < 4; it++) {
        int nl = warp + it * 8;
        int node = node0 + nl;
        float acc0 = bs[c], acc1 = bs[c + 1];
        const float* ur = u + nl * DD;
#pragma unroll 16
        for (int k = 0; k < DD; k++) {
            float uv = ur[k];
            float2 w = *(const float2*)(Ws + k * DD + c);
            acc0 += uv * w.x;
            acc1 += uv * w.y;
        }
        float2 o;
        o.x = fmaxf(acc0, 0.0f);
        o.y = fmaxf(acc1, 0.0f);
        *(float2*)(hout + (size_t)node * DD + c) = o;
        if (l < LL - 1) {
            float2 a;
            a.x = snext * o.x;
            a.y = snext * o.y;
            *(float2*)(d_agg + (size_t)node * DD + c) = a;
        }
    }
}

// ---------------- per-graph mean pool ------------------------------------
__device__ __forceinline__ int lower_bound_i(const int* a, int n, int v) {
    int lo = 0, hi = n;
    while (lo < hi) {
        int m = (lo + hi) >> 1;
        if (a[m] < v) lo = m + 1; else hi = m;
    }
    return lo;
}

__global__ void pool_kernel() {
    int g = blockIdx.x;
    int c = threadIdx.x;                 // 0..319
    int start = lower_bound_i(d_batch32, NN, g);
    int end   = lower_bound_i(d_batch32, NN, g + 1);
    int l = c >> 6, d = c & 63;
    const float* hp = d_hbuf + (size_t)l * NN * DD;
    float s = 0.0f;
    for (int n = start; n < end; n++) s += hp[(size_t)n * DD + d];
    float cnt = (float)(end - start);
    if (cnt < 1.0f) cnt = 1.0f;
    d_gpool[g * (LL * DD) + c] = s / cnt;
}

// ---------------- predictor ----------------------------------------------
__global__ void pred_kernel(const float* __restrict__ Wp,
                            const float* __restrict__ bp,
                            float* __restrict__ out) {
    int i = blockIdx.x * blockDim.x + threadIdx.x;
    if (i >= GG * TT) return;
    int g = i / TT, t = i % TT;
    float acc = __ldg(bp + t);
    const float* gp = d_gpool + g * (LL * DD);
    for (int c = 0; c < LL * DD; c++)
        acc += gp[c] * __ldg(Wp + c * TT + t);
    out[i] = acc;
}

// ---------------- launch -------------------------------------------------
extern "C" void kernel_launch(void* const* d_in, const int* in_sizes, int n_in,
                              void* d_out, int out_size) {
    const float* x     = (const float*)d_in[0];
    const void*  ei    = d_in[1];
    const float* eattr = (const float*)d_in[2];
    const void*  batch = d_in[3];
    const float* We    = (const float*)d_in[4];
    const float* be    = (const float*)d_in[5];
    const float* eps   = (const float*)d_in[6];
    const float* Wm    = (const float*)d_in[7];
    const float* bm    = (const float*)d_in[8];
    const float* Wp    = (const float*)d_in[9];
    const float* bp    = (const float*)d_in[10];
    float* out = (float*)d_out;

    detect_kernel<<<1, 32>>>((const unsigned*)ei, (const unsigned*)batch);
    convert_kernel<<<(EE + 255) / 256, 256>>>(ei, batch, eattr);

    float* hbuf = nullptr;
    cudaGetSymbolAddress((void**)&hbuf, d_hbuf);

    pre_kernel<<<(NN * DD / 4 + 255) / 256, 256>>>(x, eps);

    const float* hprev = x;
    for (int l = 0; l < LL; l++) {
        scatter_kernel<<<2048, 256>>>(hprev, We, be);
        float* hout = hbuf + (size_t)l * NN * DD;
        mlp_kernel<<<NN / 32, 256>>>(Wm + l * DD * DD, bm + l * DD, hout, eps, l);
        hprev = hout;
    }

    pool_kernel<<<GG, LL * DD>>>();
    pred_kernel<<<(GG * TT + 255) / 256, 256>>>(Wp, bp, out);
}

// round 3
// speedup vs baseline: 1.3365x; 1.0024x over previous
#include <cuda_runtime.h>

#define NN 100000
#define EE 1250000
#define DD 64
#define LL 5
#define GG 128
#define TT 37
#define DE 7
#define NCH 196          // ceil(NN/512)

// ---------------- device scratch ----------------
__device__ float d_hbuf[LL * NN * DD];    // per-layer node embeddings
__device__ float d_agg[NN * DD];
__device__ int2  d_edge[EE];              // {src,dst}
__device__ int   d_csr_src[EE];           // src ids sorted by dst
__device__ float d_eattrP[EE * 8];        // edge attrs permuted to dst order, padded
__device__ int   d_deg[NN];
__device__ int   d_off[NN];               // exclusive prefix of deg
__device__ int   d_cur[NN];
__device__ int   d_chtot[256];
__device__ int   d_choff[256];
__device__ int   d_batch32[NN];
__device__ float d_gpool[GG * LL * DD];
__device__ int   d_flags[2];

// ---------------- dtype detection ----------------
__global__ void detect_kernel(const unsigned* __restrict__ ei,
                              const unsigned* __restrict__ batch) {
    if (threadIdx.x == 0 && blockIdx.x == 0) {
        int f = 1;
        for (int k = 0; k < 64; k++)
            if (ei[1000001 + 2 * k] != 0u) { f = 0; break; }
        d_flags[0] = f;
        int fb = 1;
        for (int k = 0; k < 64; k++)
            if (batch[(NN - 1) - 2 * k] != 0u) { fb = 0; break; }
        d_flags[1] = fb;
    }
}

// ---------------- zero deg + gpool ----------------
__global__ void zero_kernel() {
    int i = blockIdx.x * blockDim.x + threadIdx.x;
    if (i < NN) d_deg[i] = 0;
    if (i < GG * LL * DD) d_gpool[i] = 0.0f;
}

// ---------------- convert indices (+ degree histogram) ----------------
__global__ void convert_kernel(const void* __restrict__ ei,
                               const void* __restrict__ batch) {
    int i = blockIdx.x * blockDim.x + threadIdx.x;
    int e64 = d_flags[0];
    int b64 = d_flags[1];
    if (i < EE) {
        int s, d;
        if (e64) {
            const long long* p = (const long long*)ei;
            s = (int)p[i]; d = (int)p[i + EE];
        } else {
            const int* p = (const int*)ei;
            s = p[i]; d = p[i + EE];
        }
        d_edge[i] = make_int2(s, d);
        atomicAdd(&d_deg[d], 1);
    }
    if (i < NN) {
        if (b64) {
            const long long* p = (const long long*)batch;
            d_batch32[i] = (int)p[i];
        } else {
            const int* p = (const int*)batch;
            d_batch32[i] = p[i];
        }
    }
}

// ---------------- scan: per-chunk exclusive scan (512/chunk) --------------
__global__ void scan1_kernel() {
    __shared__ int sm[512];
    int t = threadIdx.x;
    int g = blockIdx.x * 512 + t;
    int v = (g < NN) ? d_deg[g] : 0;
    sm[t] = v;
    __syncthreads();
    for (int off = 1; off < 512; off <<= 1) {
        int x = (t >= off) ? sm[t - off] : 0;
        __syncthreads();
        sm[t] += x;
        __syncthreads();
    }
    if (g < NN) d_off[g] = sm[t] - v;
    if (t == 511) d_chtot[blockIdx.x] = sm[511];
}

__global__ void scan2_kernel() {
    __shared__ int sm[256];
    int t = threadIdx.x;
    int v = (t < NCH) ? d_chtot[t] : 0;
    sm[t] = v;
    __syncthreads();
    for (int off = 1; off < 256; off <<= 1) {
        int x = (t >= off) ? sm[t - off] : 0;
        __syncthreads();
        sm[t] += x;
        __syncthreads();
    }
    if (t < NCH) d_choff[t] = sm[t] - v;
}

__global__ void scan3_kernel() {
    int t = threadIdx.x;
    int g = blockIdx.x * 512 + t;
    if (g < NN) {
        int o = d_off[g] + d_choff[blockIdx.x];
        d_off[g] = o;
        d_cur[g] = o;
    }
}

// ---------------- permute edges into dst-sorted order ---------------------
__global__ void csrscat_kernel(const float* __restrict__ eattr) {
    int e = blockIdx.x * blockDim.x + threadIdx.x;
    if (e >= EE) return;
    int2 sd = d_edge[e];
    int pos = atomicAdd(&d_cur[sd.y], 1);
    d_csr_src[pos] = sd.x;
    const float* ea = eattr + (size_t)e * DE;
    float4 v0 = make_float4(ea[0], ea[1], ea[2], ea[3]);
    float4 v1 = make_float4(ea[4], ea[5], ea[6], 0.0f);
    float4* p = (float4*)(d_eattrP + (size_t)pos * 8);
    p[0] = v0; p[1] = v1;
}

// ---------------- gather: agg[n] = (1+eps)*h[n] + sum relu(h[src]+emb) ----
// One warp per node, 2 cols per lane. W_edge slice lives in registers.
__global__ void __launch_bounds__(256) gather_kernel(
        const float* __restrict__ hprev,
        const float* __restrict__ We,
        const float* __restrict__ be,
        const float* __restrict__ eps, int l) {
    int wid = (blockIdx.x * blockDim.x + threadIdx.x) >> 5;
    if (wid >= NN) return;
    int lane = threadIdx.x & 31;
    int c = lane * 2;

    float2 w0 = *(const float2*)(We + 0 * DD + c);
    float2 w1 = *(const float2*)(We + 1 * DD + c);
    float2 w2 = *(const float2*)(We + 2 * DD + c);
    float2 w3 = *(const float2*)(We + 3 * DD + c);
    float2 w4 = *(const float2*)(We + 4 * DD + c);
    float2 w5 = *(const float2*)(We + 5 * DD + c);
    float2 w6 = *(const float2*)(We + 6 * DD + c);
    float2 bv = *(const float2*)(be + c);

    int start = d_off[wid];
    int end = start + d_deg[wid];

    float s0 = 0.0f, s1 = 0.0f;
    int i = start;
    // unroll by 2 for load-level parallelism
    for (; i + 2 <= end; i += 2) {
        int srcA = __ldg(&d_csr_src[i]);
        int srcB = __ldg(&d_csr_src[i + 1]);
        float4 aA0 = *(const float4*)(d_eattrP + (size_t)i * 8);
        float4 aA1 = *(const float4*)(d_eattrP + (size_t)i * 8 + 4);
        float4 aB0 = *(const float4*)(d_eattrP + (size_t)(i + 1) * 8);
        float4 aB1 = *(const float4*)(d_eattrP + (size_t)(i + 1) * 8 + 4);
        float2 hA = *(const float2*)(hprev + (size_t)srcA * DD + c);
        float2 hB = *(const float2*)(hprev + (size_t)srcB * DD + c);

        float eA0 = bv.x, eA1 = bv.y;
        eA0 = fmaf(aA0.x, w0.x, eA0); eA1 = fmaf(aA0.x, w0.y, eA1);
        eA0 = fmaf(aA0.y, w1.x, eA0); eA1 = fmaf(aA0.y, w1.y, eA1);
        eA0 = fmaf(aA0.z, w2.x, eA0); eA1 = fmaf(aA0.z, w2.y, eA1);
        eA0 = fmaf(aA0.w, w3.x, eA0); eA1 = fmaf(aA0.w, w3.y, eA1);
        eA0 = fmaf(aA1.x, w4.x, eA0); eA1 = fmaf(aA1.x, w4.y, eA1);
        eA0 = fmaf(aA1.y, w5.x, eA0); eA1 = fmaf(aA1.y, w5.y, eA1);
        eA0 = fmaf(aA1.z, w6.x, eA0); eA1 = fmaf(aA1.z, w6.y, eA1);
        s0 += fmaxf(eA0 + hA.x, 0.0f);
        s1 += fmaxf(eA1 + hA.y, 0.0f);

        float eB0 = bv.x, eB1 = bv.y;
        eB0 = fmaf(aB0.x, w0.x, eB0); eB1 = fmaf(aB0.x, w0.y, eB1);
        eB0 = fmaf(aB0.y, w1.x, eB0); eB1 = fmaf(aB0.y, w1.y, eB1);
        eB0 = fmaf(aB0.z, w2.x, eB0); eB1 = fmaf(aB0.z, w2.y, eB1);
        eB0 = fmaf(aB0.w, w3.x, eB0); eB1 = fmaf(aB0.w, w3.y, eB1);
        eB0 = fmaf(aB1.x, w4.x, eB0); eB1 = fmaf(aB1.x, w4.y, eB1);
        eB0 = fmaf(aB1.y, w5.x, eB0); eB1 = fmaf(aB1.y, w5.y, eB1);
        eB0 = fmaf(aB1.z, w6.x, eB0); eB1 = fmaf(aB1.z, w6.y, eB1);
        s0 += fmaxf(eB0 + hB.x, 0.0f);
        s1 += fmaxf(eB1 + hB.y, 0.0f);
    }
    if (i < end) {
        int src = __ldg(&d_csr_src[i]);
        float4 a0 = *(const float4*)(d_eattrP + (size_t)i * 8);
        float4 a1 = *(const float4*)(d_eattrP + (size_t)i * 8 + 4);
        float2 hv = *(const float2*)(hprev + (size_t)src * DD + c);
        float e0 = bv.x, e1 = bv.y;
        e0 = fmaf(a0.x, w0.x, e0); e1 = fmaf(a0.x, w0.y, e1);
        e0 = fmaf(a0.y, w1.x, e0); e1 = fmaf(a0.y, w1.y, e1);
        e0 = fmaf(a0.z, w2.x, e0); e1 = fmaf(a0.z, w2.y, e1);
        e0 = fmaf(a0.w, w3.x, e0); e1 = fmaf(a0.w, w3.y, e1);
        e0 = fmaf(a1.x, w4.x, e0); e1 = fmaf(a1.x, w4.y, e1);
        e0 = fmaf(a1.y, w5.x, e0); e1 = fmaf(a1.y, w5.y, e1);
        e0 = fmaf(a1.z, w6.x, e0); e1 = fmaf(a1.z, w6.y, e1);
        s0 += fmaxf(e0 + hv.x, 0.0f);
        s1 += fmaxf(e1 + hv.y, 0.0f);
    }

    float se = 1.0f + __ldg(eps + l);
    float2 h = *(const float2*)(hprev + (size_t)wid * DD + c);
    float2 o;
    o.x = fmaf(se, h.x, s0);
    o.y = fmaf(se, h.y, s1);
    *(float2*)(d_agg + (size_t)wid * DD + c) = o;
}

// ---------------- MLP: h_out = relu(agg @ W + b), 4x4 register blocking ---
__global__ void __launch_bounds__(256) mlp_kernel(
        const float* __restrict__ W,
        const float* __restrict__ b,
        float* __restrict__ hout) {
    __shared__ float Ws[DD * DD];
    __shared__ float bs[DD];
    __shared__ float u[64 * DD];

    int t = threadIdx.x;
    for (int i = t; i < DD * DD / 4; i += 256)
        ((float4*)Ws)[i] = ((const float4*)W)[i];
    if (t < DD) bs[t] = b[t];

    int node0 = blockIdx.x * 64;
    for (int i = t; i < 64 * 16; i += 256) {
        int node = node0 + (i >> 4);
        float4 v = (node < NN)
            ? ((const float4*)(d_agg + (size_t)node * DD))[i & 15]
            : make_float4(0.f, 0.f, 0.f, 0.f);
        ((float4*)u)[i] = v;
    }
    __syncthreads();

    int c4 = (t & 15) * 4;
    int n4 = (t >> 4) * 4;

    float acc[4][4];
#pragma unroll
    for (int ni = 0; ni < 4; ni++) {
        acc[ni][0] = bs[c4 + 0];
        acc[ni][1] = bs[c4 + 1];
        acc[ni][2] = bs[c4 + 2];
        acc[ni][3] = bs[c4 + 3];
    }

#pragma unroll 8
    for (int k = 0; k < DD; k++) {
        float4 w = *(const float4*)(Ws + k * DD + c4);
#pragma unroll
        for (int ni = 0; ni < 4; ni++) {
            float uv = u[(n4 + ni) * DD + k];
            acc[ni][0] = fmaf(uv, w.x, acc[ni][0]);
            acc[ni][1] = fmaf(uv, w.y, acc[ni][1]);
            acc[ni][2] = fmaf(uv, w.z, acc[ni][2]);
            acc[ni][3] = fmaf(uv, w.w, acc[ni][3]);
        }
    }

#pragma unroll
    for (int ni = 0; ni < 4; ni++) {
        int node = node0 + n4 + ni;
        if (node < NN) {
            float4 o;
            o.x = fmaxf(acc[ni][0], 0.0f);
            o.y = fmaxf(acc[ni][1], 0.0f);
            o.z = fmaxf(acc[ni][2], 0.0f);
            o.w = fmaxf(acc[ni][3], 0.0f);
            *(float4*)(hout + (size_t)node * DD + c4) = o;
        }
    }
}

// ---------------- pool: chunked partial sums + atomic flush ---------------
__global__ void pool_kernel() {
    int c = threadIdx.x;                  // 0..319
    int l = c >> 6, d = c & 63;
    int n0 = blockIdx.x * 256;
    int n1 = min(n0 + 256, NN);
    if (n0 >= NN) return;
    const float* hp = d_hbuf + (size_t)l * NN * DD;
    float s = 0.0f;
    int curg = d_batch32[n0];
    for (int n = n0; n < n1; n++) {
        int g = d_batch32[n];
        if (g != curg) {
            atomicAdd(&d_gpool[curg * (LL * DD) + c], s);
            s = 0.0f;
            curg = g;
        }
        s += hp[(size_t)n * DD + d];
    }
    atomicAdd(&d_gpool[curg * (LL * DD) + c], s);
}

// ---------------- predictor (divides by count) ----------------------------
__device__ __forceinline__ int lower_bound_i(const int* a, int n, int v) {
    int lo = 0, hi = n;
    while (lo < hi) {
        int m = (lo + hi) >> 1;
        if (a[m] < v) lo = m + 1; else hi = m;
    }
    return lo;
}

__global__ void pred_kernel(const float* __restrict__ Wp,
                            const float* __restrict__ bp,
                            float* __restrict__ out) {
    int i = blockIdx.x * blockDim.x + threadIdx.x;
    if (i >= GG * TT) return;
    int g = i / TT, t = i % TT;
    int start = lower_bound_i(d_batch32, NN, g);
    int end   = lower_bound_i(d_batch32, NN, g + 1);
    int cnt = end - start;
    float inv = 1.0f / (float)(cnt > 0 ? cnt : 1);
    const float* gp = d_gpool + g * (LL * DD);
    float s = 0.0f;
    for (int c = 0; c < LL * DD; c++)
        s = fmaf(gp[c], __ldg(Wp + c * TT + t), s);
    out[i] = fmaf(inv, s, __ldg(bp + t));
}

// ---------------- launch -------------------------------------------------
extern "C" void kernel_launch(void* const* d_in, const int* in_sizes, int n_in,
                              void* d_out, int out_size) {
    const float* x     = (const float*)d_in[0];
    const void*  ei    = d_in[1];
    const float* eattr = (const float*)d_in[2];
    const void*  batch = d_in[3];
    const float* We    = (const float*)d_in[4];
    const float* be    = (const float*)d_in[5];
    const float* eps   = (const float*)d_in[6];
    const float* Wm    = (const float*)d_in[7];
    const float* bm    = (const float*)d_in[8];
    const float* Wp    = (const float*)d_in[9];
    const float* bp    = (const float*)d_in[10];
    float* out = (float*)d_out;

    detect_kernel<<<1, 32>>>((const unsigned*)ei, (const unsigned*)batch);
    zero_kernel<<<(NN + 255) / 256, 256>>>();
    convert_kernel<<<(EE + 255) / 256, 256>>>(ei, batch);
    scan1_kernel<<<NCH, 512>>>();
    scan2_kernel<<<1, 256>>>();
    scan3_kernel<<<NCH, 512>>>();
    csrscat_kernel<<<(EE + 255) / 256, 256>>>(eattr);

    float* hbuf = nullptr;
    cudaGetSymbolAddress((void**)&hbuf, d_hbuf);

    const float* hprev = x;
    for (int l = 0; l < LL; l++) {
        gather_kernel<<<(NN * 32 + 255) / 256, 256>>>(hprev, We, be, eps, l);
        float* hout = hbuf + (size_t)l * NN * DD;
        mlp_kernel<<<(NN + 63) / 64, 256>>>(Wm + l * DD * DD, bm + l * DD, hout);
        hprev = hout;
    }

    pool_kernel<<<(NN + 255) / 256, 320>>>();
    pred_kernel<<<(GG * TT + 255) / 256, 256>>>(Wp, bp, out);
}

// round 4
// speedup vs baseline: 1.9481x; 1.4576x over previous
#include <cuda_runtime.h>

#define NN 100000
#define EE 1250000
#define DD 64
#define LL 5
#define GG 128
#define TT 37
#define DE 7
#define NCH 196          // ceil(NN/512)

#define SC_BLOCKS 1024
#define SC_HW (SC_BLOCKS * 16)            // half-warps in scatter grid
#define EPH ((EE + SC_HW - 1) / SC_HW)    // edges per half-warp chunk

// ---------------- device scratch ----------------
__device__ float d_hbuf[LL * NN * DD];    // per-layer node embeddings
__device__ float d_agg[NN * DD];
__device__ int2  d_edge[EE];              // raw {src,dst}
__device__ int2  d_edgeP[EE];             // {src,dst} sorted by src
__device__ float d_eattrP[EE * 8];        // edge attrs permuted to src order
__device__ int   d_deg[NN];               // out-degree
__device__ int   d_off[NN];
__device__ int   d_cur[NN];
__device__ int   d_chtot[256];
__device__ int   d_choff[256];
__device__ int   d_batch32[NN];
__device__ float d_gpool[GG * LL * DD];
__device__ int   d_flags[2];

// ---------------- dtype detection ----------------
__global__ void detect_kernel(const unsigned* __restrict__ ei,
                              const unsigned* __restrict__ batch) {
    if (threadIdx.x == 0 && blockIdx.x == 0) {
        int f = 1;
        for (int k = 0; k < 64; k++)
            if (ei[1000001 + 2 * k] != 0u) { f = 0; break; }
        d_flags[0] = f;
        int fb = 1;
        for (int k = 0; k < 64; k++)
            if (batch[(NN - 1) - 2 * k] != 0u) { fb = 0; break; }
        d_flags[1] = fb;
    }
}

// ---------------- zero deg + gpool ----------------
__global__ void zero_kernel() {
    int i = blockIdx.x * blockDim.x + threadIdx.x;
    if (i < NN) d_deg[i] = 0;
    if (i < GG * LL * DD) d_gpool[i] = 0.0f;
}

// ---------------- convert indices (+ out-degree histogram) ----------------
__global__ void convert_kernel(const void* __restrict__ ei,
                               const void* __restrict__ batch) {
    int i = blockIdx.x * blockDim.x + threadIdx.x;
    int e64 = d_flags[0];
    int b64 = d_flags[1];
    if (i < EE) {
        int s, d;
        if (e64) {
            const long long* p = (const long long*)ei;
            s = (int)p[i]; d = (int)p[i + EE];
        } else {
            const int* p = (const int*)ei;
            s = p[i]; d = p[i + EE];
        }
        d_edge[i] = make_int2(s, d);
        atomicAdd(&d_deg[s], 1);
    }
    if (i < NN) {
        if (b64) {
            const long long* p = (const long long*)batch;
            d_batch32[i] = (int)p[i];
        } else {
            const int* p = (const int*)batch;
            d_batch32[i] = p[i];
        }
    }
}

// ---------------- scans ----------------
__global__ void scan1_kernel() {
    __shared__ int sm[512];
    int t = threadIdx.x;
    int g = blockIdx.x * 512 + t;
    int v = (g < NN) ? d_deg[g] : 0;
    sm[t] = v;
    __syncthreads();
    for (int off = 1; off < 512; off <<= 1) {
        int x = (t >= off) ? sm[t - off] : 0;
        __syncthreads();
        sm[t] += x;
        __syncthreads();
    }
    if (g < NN) d_off[g] = sm[t] - v;
    if (t == 511) d_chtot[blockIdx.x] = sm[511];
}

__global__ void scan2_kernel() {
    __shared__ int sm[256];
    int t = threadIdx.x;
    int v = (t < NCH) ? d_chtot[t] : 0;
    sm[t] = v;
    __syncthreads();
    for (int off = 1; off < 256; off <<= 1) {
        int x = (t >= off) ? sm[t - off] : 0;
        __syncthreads();
        sm[t] += x;
        __syncthreads();
    }
    if (t < NCH) d_choff[t] = sm[t] - v;
}

__global__ void scan3_kernel() {
    int t = threadIdx.x;
    int g = blockIdx.x * 512 + t;
    if (g < NN) {
        int o = d_off[g] + d_choff[blockIdx.x];
        d_off[g] = o;
        d_cur[g] = o;
    }
}

// ---------------- permute edges into src-sorted order ---------------------
__global__ void csrscat_kernel(const float* __restrict__ eattr) {
    int e = blockIdx.x * blockDim.x + threadIdx.x;
    if (e >= EE) return;
    int2 sd = d_edge[e];
    int pos = atomicAdd(&d_cur[sd.x], 1);
    d_edgeP[pos] = sd;
    const float* ea = eattr + (size_t)e * DE;
    float4 v0 = make_float4(ea[0], ea[1], ea[2], ea[3]);
    float4 v1 = make_float4(ea[4], ea[5], ea[6], 0.0f);
    float4* p = (float4*)(d_eattrP + (size_t)pos * 8);
    p[0] = v0; p[1] = v1;
}

// ---------------- agg = (1 + eps[0]) * x  (layer 0 only) ------------------
__global__ void pre_kernel(const float* __restrict__ hprev,
                           const float* __restrict__ eps) {
    int i = blockIdx.x * blockDim.x + threadIdx.x;
    const int n4 = NN * DD / 4;
    if (i >= n4) return;
    float s = 1.0f + __ldg(eps);
    float4 v = ((const float4*)hprev)[i];
    v.x *= s; v.y *= s; v.z *= s; v.w *= s;
    ((float4*)d_agg)[i] = v;
}

// ---------------- scatter: agg[dst] += relu(h[src] + edge_emb) ------------
// Edges sorted by src; each half-warp owns a CONTIGUOUS chunk so h[src]
// loads hit L1 (~92% of edges reuse the previous row). RED is fire-and-forget.
__global__ void __launch_bounds__(256) scatter_kernel(
        const float* __restrict__ hprev,
        const float* __restrict__ We,
        const float* __restrict__ be) {
    int lane = threadIdx.x & 31;
    int c = (lane & 15) * 4;

    float4 w0 = *(const float4*)(We + 0 * DD + c);
    float4 w1 = *(const float4*)(We + 1 * DD + c);
    float4 w2 = *(const float4*)(We + 2 * DD + c);
    float4 w3 = *(const float4*)(We + 3 * DD + c);
    float4 w4 = *(const float4*)(We + 4 * DD + c);
    float4 w5 = *(const float4*)(We + 5 * DD + c);
    float4 w6 = *(const float4*)(We + 6 * DD + c);
    float4 bv = *(const float4*)(be + c);

    int hwid = (blockIdx.x * blockDim.x + threadIdx.x) >> 4;
    long long e0 = (long long)hwid * EPH;
    long long e1 = e0 + EPH;
    if (e1 > EE) e1 = EE;

#pragma unroll 2
    for (long long e = e0; e < e1; e++) {
        int2 sd = __ldg(&d_edgeP[e]);
        float4 a0 = __ldg((const float4*)(d_eattrP + (size_t)e * 8));
        float4 a1 = __ldg((const float4*)(d_eattrP + (size_t)e * 8 + 4));
        float4 hv = __ldg((const float4*)(hprev + (size_t)sd.x * DD + c));

        float m0 = bv.x, m1 = bv.y, m2 = bv.z, m3 = bv.w;
        m0 = fmaf(a0.x, w0.x, m0); m1 = fmaf(a0.x, w0.y, m1);
        m2 = fmaf(a0.x, w0.z, m2); m3 = fmaf(a0.x, w0.w, m3);
        m0 = fmaf(a0.y, w1.x, m0); m1 = fmaf(a0.y, w1.y, m1);
        m2 = fmaf(a0.y, w1.z, m2); m3 = fmaf(a0.y, w1.w, m3);
        m0 = fmaf(a0.z, w2.x, m0); m1 = fmaf(a0.z, w2.y, m1);
        m2 = fmaf(a0.z, w2.z, m2); m3 = fmaf(a0.z, w2.w, m3);
        m0 = fmaf(a0.w, w3.x, m0); m1 = fmaf(a0.w, w3.y, m1);
        m2 = fmaf(a0.w, w3.z, m2); m3 = fmaf(a0.w, w3.w, m3);
        m0 = fmaf(a1.x, w4.x, m0); m1 = fmaf(a1.x, w4.y, m1);
        m2 = fmaf(a1.x, w4.z, m2); m3 = fmaf(a1.x, w4.w, m3);
        m0 = fmaf(a1.y, w5.x, m0); m1 = fmaf(a1.y, w5.y, m1);
        m2 = fmaf(a1.y, w5.z, m2); m3 = fmaf(a1.y, w5.w, m3);
        m0 = fmaf(a1.z, w6.x, m0); m1 = fmaf(a1.z, w6.y, m1);
        m2 = fmaf(a1.z, w6.z, m2); m3 = fmaf(a1.z, w6.w, m3);

        m0 = fmaxf(m0 + hv.x, 0.0f);
        m1 = fmaxf(m1 + hv.y, 0.0f);
        m2 = fmaxf(m2 + hv.z, 0.0f);
        m3 = fmaxf(m3 + hv.w, 0.0f);

        float* ap = d_agg + (size_t)sd.y * DD + c;
        asm volatile("red.global.add.v4.f32 [%0], {%1,%2,%3,%4};"
                     :: "l"(ap), "f"(m0), "f"(m1), "f"(m2), "f"(m3)
                     : "memory");
    }
}

// ---------------- MLP: h_out = relu(agg @ W + b); agg_next = s*h_out ------
__global__ void __launch_bounds__(256) mlp_kernel(
        const float* __restrict__ W,
        const float* __restrict__ b,
        float* __restrict__ hout,
        const float* __restrict__ eps, int l) {
    __shared__ float Ws[DD * DD];
    __shared__ float bs[DD];
    __shared__ float u[64 * DD];

    int t = threadIdx.x;
    for (int i = t; i < DD * DD / 4; i += 256)
        ((float4*)Ws)[i] = ((const float4*)W)[i];
    if (t < DD) bs[t] = b[t];

    int node0 = blockIdx.x * 64;
    for (int i = t; i < 64 * 16; i += 256) {
        int node = node0 + (i >> 4);
        float4 v = (node < NN)
            ? ((const float4*)(d_agg + (size_t)node * DD))[i & 15]
            : make_float4(0.f, 0.f, 0.f, 0.f);
        ((float4*)u)[i] = v;
    }
    __syncthreads();

    float snext = (l < LL - 1) ? (1.0f + __ldg(eps + l + 1)) : 0.0f;

    int c4 = (t & 15) * 4;
    int n4 = (t >> 4) * 4;

    float acc[4][4];
#pragma unroll
    for (int ni = 0; ni < 4; ni++) {
        acc[ni][0] = bs[c4 + 0];
        acc[ni][1] = bs[c4 + 1];
        acc[ni][2] = bs[c4 + 2];
        acc[ni][3] = bs[c4 + 3];
    }

#pragma unroll 8
    for (int k = 0; k < DD; k++) {
        float4 w = *(const float4*)(Ws + k * DD + c4);
#pragma unroll
        for (int ni = 0; ni < 4; ni++) {
            float uv = u[(n4 + ni) * DD + k];
            acc[ni][0] = fmaf(uv, w.x, acc[ni][0]);
            acc[ni][1] = fmaf(uv, w.y, acc[ni][1]);
            acc[ni][2] = fmaf(uv, w.z, acc[ni][2]);
            acc[ni][3] = fmaf(uv, w.w, acc[ni][3]);
        }
    }

#pragma unroll
    for (int ni = 0; ni < 4; ni++) {
        int node = node0 + n4 + ni;
        if (node < NN) {
            float4 o;
            o.x = fmaxf(acc[ni][0], 0.0f);
            o.y = fmaxf(acc[ni][1], 0.0f);
            o.z = fmaxf(acc[ni][2], 0.0f);
            o.w = fmaxf(acc[ni][3], 0.0f);
            *(float4*)(hout + (size_t)node * DD + c4) = o;
            if (l < LL - 1) {
                float4 a;
                a.x = snext * o.x; a.y = snext * o.y;
                a.z = snext * o.z; a.w = snext * o.w;
                *(float4*)(d_agg + (size_t)node * DD + c4) = a;
            }
        }
    }
}

// ---------------- pool: chunked partial sums + atomic flush ---------------
__global__ void pool_kernel() {
    int c = threadIdx.x;                  // 0..319
    int l = c >> 6, d = c & 63;
    int n0 = blockIdx.x * 256;
    int n1 = min(n0 + 256, NN);
    if (n0 >= NN) return;
    const float* hp = d_hbuf + (size_t)l * NN * DD;
    float s = 0.0f;
    int curg = d_batch32[n0];
    for (int n = n0; n < n1; n++) {
        int g = d_batch32[n];
        if (g != curg) {
            atomicAdd(&d_gpool[curg * (LL * DD) + c], s);
            s = 0.0f;
            curg = g;
        }
        s += hp[(size_t)n * DD + d];
    }
    atomicAdd(&d_gpool[curg * (LL * DD) + c], s);
}

// ---------------- predictor ----------------------------------------------
__device__ __forceinline__ int lower_bound_i(const int* a, int n, int v) {
    int lo = 0, hi = n;
    while (lo < hi) {
        int m = (lo + hi) >> 1;
        if (a[m] < v) lo = m + 1; else hi = m;
    }
    return lo;
}

__global__ void pred_kernel(const float* __restrict__ Wp,
                            const float* __restrict__ bp,
                            float* __restrict__ out) {
    int i = blockIdx.x * blockDim.x + threadIdx.x;
    if (i >= GG * TT) return;
    int g = i / TT, t = i % TT;
    int start = lower_bound_i(d_batch32, NN, g);
    int end   = lower_bound_i(d_batch32, NN, g + 1);
    int cnt = end - start;
    float inv = 1.0f / (float)(cnt > 0 ? cnt : 1);
    const float* gp = d_gpool + g * (LL * DD);
    float s = 0.0f;
    for (int c = 0; c < LL * DD; c++)
        s = fmaf(gp[c], __ldg(Wp + c * TT + t), s);
    out[i] = fmaf(inv, s, __ldg(bp + t));
}

// ---------------- launch -------------------------------------------------
extern "C" void kernel_launch(void* const* d_in, const int* in_sizes, int n_in,
                              void* d_out, int out_size) {
    const float* x     = (const float*)d_in[0];
    const void*  ei    = d_in[1];
    const float* eattr = (const float*)d_in[2];
    const void*  batch = d_in[3];
    const float* We    = (const float*)d_in[4];
    const float* be    = (const float*)d_in[5];
    const float* eps   = (const float*)d_in[6];
    const float* Wm    = (const float*)d_in[7];
    const float* bm    = (const float*)d_in[8];
    const float* Wp    = (const float*)d_in[9];
    const float* bp    = (const float*)d_in[10];
    float* out = (float*)d_out;

    detect_kernel<<<1, 32>>>((const unsigned*)ei, (const unsigned*)batch);
    zero_kernel<<<(NN + 255) / 256, 256>>>();
    convert_kernel<<<(EE + 255) / 256, 256>>>(ei, batch);
    scan1_kernel<<<NCH, 512>>>();
    scan2_kernel<<<1, 256>>>();
    scan3_kernel<<<NCH, 512>>>();
    csrscat_kernel<<<(EE + 255) / 256, 256>>>(eattr);

    float* hbuf = nullptr;
    cudaGetSymbolAddress((void**)&hbuf, d_hbuf);

    pre_kernel<<<(NN * DD / 4 + 255) / 256, 256>>>(x, eps);

    const float* hprev = x;
    for (int l = 0; l < LL; l++) {
        scatter_kernel<<<SC_BLOCKS, 256>>>(hprev, We, be);
        float* hout = hbuf + (size_t)l * NN * DD;
        mlp_kernel<<<(NN + 63) / 64, 256>>>(Wm + l * DD * DD, bm + l * DD, hout, eps, l);
        hprev = hout;
    }

    pool_kernel<<<(NN + 255) / 256, 320>>>();
    pred_kernel<<<(GG * TT + 255) / 256, 256>>>(Wp, bp, out);
}